// round 14
// baseline (speedup 1.0000x reference)
#include <cuda_runtime.h>
#include <cstdint>
#include <math.h>

// Problem constants (fixed by the reference: D=1024, R=4096)
#define D 1024
#define R 4096
#define TT (D - 1)
#define TCHUNK 8
#define NCHUNKS 128             // 128*8 = 1024 >= 1023

#define ISCALE    0.0078125f    // 2^-7 pre-scale of I into e4m3 range
#define ISCALE_INV 128.f

// ---------------- scratch (no allocation allowed) ----------------
__device__ float g_AI[(size_t)D * R];                 // 16 MB
__device__ float g_AN[R];
__device__ float g_partialA[NCHUNKS * R];             // EIT partials
__device__ float g_partialB[NCHUNKS * R];             // S partials
__device__ uint8_t g_I8[(size_t)D * R];               // 4 MB  (e4m3)
__device__ uint8_t g_ADJ8[(size_t)R * R];             // 16 MB (e4m3)

// ================= PTX helpers (sm_89-class max; no 'a'-gated features) ========
__device__ __forceinline__ uint32_t smem_u32(const void* p) {
    uint32_t a;
    asm("{ .reg .u64 t; cvta.to.shared.u64 t, %1; cvt.u32.u64 %0, t; }" : "=r"(a) : "l"(p));
    return a;
}

#define CPASYNC16(saddr, gaddr) \
    asm volatile("cp.async.cg.shared.global [%0], [%1], 16;" :: "r"(saddr), "l"(gaddr) : "memory")
#define CPASYNC_COMMIT() asm volatile("cp.async.commit_group;" ::: "memory")
#define CPASYNC_WAIT2()  asm volatile("cp.async.wait_group 2;" ::: "memory")

#define LDSM_X4(r0, r1, r2, r3, addr) \
    asm volatile("ldmatrix.sync.aligned.m8n8.x4.shared.b16 {%0,%1,%2,%3}, [%4];" \
                 : "=r"(r0), "=r"(r1), "=r"(r2), "=r"(r3) : "r"(addr))

#define MMA_FP8(c, a0, a1, a2, a3, b0, b1) \
    asm volatile("mma.sync.aligned.m16n8k32.row.col.f32.e4m3.e4m3.f32 " \
                 "{%0,%1,%2,%3}, {%4,%5,%6,%7}, {%8,%9}, {%0,%1,%2,%3};" \
                 : "+f"((c)[0]), "+f"((c)[1]), "+f"((c)[2]), "+f"((c)[3]) \
                 : "r"(a0), "r"(a1), "r"(a2), "r"(a3), "r"(b0), "r"(b1))

__device__ __forceinline__ uint32_t pack4_e4m3(float f0, float f1, float f2, float f3) {
    uint16_t lo, hi;
    asm("cvt.rn.satfinite.e4m3x2.f32 %0, %1, %2;" : "=h"(lo) : "f"(f1), "f"(f0));
    asm("cvt.rn.satfinite.e4m3x2.f32 %0, %1, %2;" : "=h"(hi) : "f"(f3), "f"(f2));
    return (uint32_t)lo | ((uint32_t)hi << 16);
}

// ---------------- fused adj: f32->e4m3 convert + AN[r] = adj[r,:] . N ----------
__global__ void __launch_bounds__(128) cvt_adj_an(
    const float* __restrict__ adj, const float* __restrict__ Nv,
    uint8_t* __restrict__ dst)
{
    __shared__ float wsum[4];
    const int r = blockIdx.x;
    const float* row = adj + (size_t)r * R;
    uint8_t* orow = dst + (size_t)r * R;

    float s = 0.f;
    #pragma unroll
    for (int it = 0; it < R / (128 * 8); it++) {
        int q = (it * 128 + threadIdx.x) * 8;
        float4 a = *(const float4*)(row + q);
        float4 b = *(const float4*)(row + q + 4);
        float4 n0 = *(const float4*)(Nv + q);
        float4 n1 = *(const float4*)(Nv + q + 4);
        uint2 o;
        o.x = pack4_e4m3(a.x, a.y, a.z, a.w);
        o.y = pack4_e4m3(b.x, b.y, b.z, b.w);
        *(uint2*)(orow + q) = o;
        s = fmaf(a.x, n0.x, s); s = fmaf(a.y, n0.y, s);
        s = fmaf(a.z, n0.z, s); s = fmaf(a.w, n0.w, s);
        s = fmaf(b.x, n1.x, s); s = fmaf(b.y, n1.y, s);
        s = fmaf(b.z, n1.z, s); s = fmaf(b.w, n1.w, s);
    }
    #pragma unroll
    for (int o = 16; o; o >>= 1) s += __shfl_down_sync(0xffffffffu, s, o);
    int lane = threadIdx.x & 31, wid = threadIdx.x >> 5;
    if (lane == 0) wsum[wid] = s;
    __syncthreads();
    if (threadIdx.x == 0)
        g_AN[r] = wsum[0] + wsum[1] + wsum[2] + wsum[3];
}

// ---------------- I: f32 -> e4m3 with 2^-7 scale ----------------
__global__ void cvt_I8(const float* __restrict__ src, uint8_t* __restrict__ dst, int n8) {
    int i = blockIdx.x * blockDim.x + threadIdx.x;
    int stride = gridDim.x * blockDim.x;
    for (; i < n8; i += stride) {
        float4 v0 = ((const float4*)src)[2 * i];
        float4 v1 = ((const float4*)src)[2 * i + 1];
        uint2 o;
        o.x = pack4_e4m3(v0.x * ISCALE, v0.y * ISCALE, v0.z * ISCALE, v0.w * ISCALE);
        o.y = pack4_e4m3(v1.x * ISCALE, v1.y * ISCALE, v1.z * ISCALE, v1.w * ISCALE);
        ((uint2*)dst)[i] = o;
    }
}

// ================= e4m3 GEMM: AI = 128 * I8 @ ADJ8^T =================
// 64x64 tiles, 128 threads (2x2 warps of 32x32), 1024 CTAs, 4-stage pipeline,
// single barrier per k-iter, all LDSM addresses hoisted out of the k-loop.
#define BM 64
#define BN 64
#define BK 128                  // e4m3 elements per chunk: 128 B per row
#define NKC (R / BK)            // 32 k-chunks
#define NSTG 4
#define A_STG 8192              // 64 rows x 128 B
#define STG   16384             // A + B
#define GEMM_SMEM (NSTG * STG)  // 65536 B

__global__ void __launch_bounds__(128) gemm_mma(
    const uint8_t* __restrict__ A, const uint8_t* __restrict__ B,
    float* __restrict__ C)
{
    extern __shared__ char smem[];
    const uint32_t sbase = smem_u32(smem);
    const int tid  = threadIdx.x;
    const int lane = tid & 31;
    const int wid  = tid >> 5;
    const int bm = blockIdx.y * BM;
    const int bn = blockIdx.x * BN;

    // ---- producer: each of 128 threads loads 4 A segs + 4 B segs (16B each) ----
    uint64_t gpA[4], gpB[4];
    uint32_t soA[4], soB[4];
    #pragma unroll
    for (int j = 0; j < 4; j++) {
        int s = tid + j * 128;          // 0..511
        int row = s >> 3, pc = s & 7;
        gpA[j] = (uint64_t)(A + (size_t)(bm + row) * R + pc * 16);
        gpB[j] = (uint64_t)(B + (size_t)(bn + row) * R + pc * 16);
        soA[j] = (uint32_t)(row * 128 + ((pc ^ (row & 7)) << 4));
        soB[j] = soA[j] + A_STG;
    }

#define ISSUE_STAGE(kt, s)                                              \
    do {                                                                \
        uint32_t dst = sbase + (s) * STG;                               \
        _Pragma("unroll")                                               \
        for (int j = 0; j < 4; j++) {                                   \
            CPASYNC16(dst + soA[j], gpA[j] + (size_t)(kt) * BK);        \
            CPASYNC16(dst + soB[j], gpB[j] + (size_t)(kt) * BK);        \
        }                                                               \
    } while (0)

    // ---- consumer: 2x2 warps, each 32x32; hoist ALL ldsm addresses ----
    const int wm = (wid & 1) * 32;
    const int wn = (wid >> 1) * 32;
    const int l15 = lane & 15;
    const int lhi = lane >> 4;
    const int l7  = lane & 7;

    // offA[fm][kk], offB[nb][kk]: smem offsets within a stage (stage base added in loop)
    uint32_t offA[2][4], offB[2][4];
    #pragma unroll
    for (int kk = 0; kk < 4; kk++) {
        const uint32_t sw = (uint32_t)(((kk * 2 + lhi) ^ l7)) << 4;
        #pragma unroll
        for (int fm = 0; fm < 2; fm++)
            offA[fm][kk] = (uint32_t)(wm + fm * 16 + l15) * 128 + sw;
        #pragma unroll
        for (int nb = 0; nb < 2; nb++)
            offB[nb][kk] = (uint32_t)(wn + nb * 16 + l15) * 128 + A_STG + sw;
    }

    float c[2][4][4];
    #pragma unroll
    for (int fm = 0; fm < 2; fm++)
        #pragma unroll
        for (int nf = 0; nf < 4; nf++)
            #pragma unroll
            for (int v = 0; v < 4; v++) c[fm][nf][v] = 0.f;

    ISSUE_STAGE(0, 0); CPASYNC_COMMIT();
    ISSUE_STAGE(1, 1); CPASYNC_COMMIT();
    ISSUE_STAGE(2, 2); CPASYNC_COMMIT();

    for (int kt = 0; kt < NKC; kt++) {
        const int s = kt & (NSTG - 1);
        CPASYNC_WAIT2();
        __syncthreads();   // single barrier: stage-s visible AND prev reads done

        if (kt + 3 < NKC) { ISSUE_STAGE(kt + 3, (kt + 3) & (NSTG - 1)); }
        CPASYNC_COMMIT();

        const uint32_t st = sbase + s * STG;
        #pragma unroll
        for (int kk = 0; kk < 4; kk++) {   // 4 x k32 per 128B chunk
            uint32_t a[2][4], bq[2][4];
            #pragma unroll
            for (int fm = 0; fm < 2; fm++)
                LDSM_X4(a[fm][0], a[fm][1], a[fm][2], a[fm][3], st + offA[fm][kk]);
            #pragma unroll
            for (int nb = 0; nb < 2; nb++)
                LDSM_X4(bq[nb][0], bq[nb][1], bq[nb][2], bq[nb][3], st + offB[nb][kk]);

            #pragma unroll
            for (int fm = 0; fm < 2; fm++)
                #pragma unroll
                for (int nf = 0; nf < 4; nf++) {
                    const int nb = nf >> 1, od = nf & 1;
                    MMA_FP8(c[fm][nf], a[fm][0], a[fm][1], a[fm][2], a[fm][3],
                            bq[nb][od], bq[nb][od + 2]);
                }
        }
        // no trailing barrier: next iteration's top barrier orders the
        // stage rewrite (prefetch distance 3 with 4 stages keeps it safe)
    }

    // ---- epilogue (rescale by 2^7) ----
    const int g  = lane >> 2;
    const int t2 = (lane & 3) * 2;
    #pragma unroll
    for (int fm = 0; fm < 2; fm++) {
        float* p0 = C + (size_t)(bm + wm + fm * 16 + g) * R + bn + wn + t2;
        #pragma unroll
        for (int nf = 0; nf < 4; nf++) {
            *(float2*)(p0 + nf * 8) =
                make_float2(c[fm][nf][0] * ISCALE_INV, c[fm][nf][1] * ISCALE_INV);
            *(float2*)(p0 + 8 * R + nf * 8) =
                make_float2(c[fm][nf][2] * ISCALE_INV, c[fm][nf][3] * ISCALE_INV);
        }
    }
#undef ISSUE_STAGE
}

// ---------------- elementwise log-probs ----------------
#define LOG2PI 1.8378770664093454836f

__device__ __forceinline__ float lp_eit(
    float e, float i, float tt,
    float ei, float it, float iu, float tr, float td,
    float det, float rec, float dE, float dI, float dT)
{
    float mE  = e * dE;
    float covE = mE * (1.f - dE);
    float dEe = ei - mE;
    float quadE = __fdividef(dEe * dEe, covE);

    float p1 = det * dI, p2 = (1.f - det) * dI;
    float m1 = i * p1, m2 = i * p2;
    float d1 = it - m1, d2 = iu - m2;
    float c11 = m1 * (1.f - p1);
    float c22 = m2 * (1.f - p2);
    float c12 = -(m1 * p2);
    float detI = i * m1 * p2 * (1.f - p1 - p2);
    float quadI = __fdividef(d1 * d1 * c22 - 2.f * d1 * d2 * c12 + d2 * d2 * c11, detI);

    float q1 = rec * dT, q2 = (1.f - rec) * dT;
    float n1 = tt * q1, n2 = tt * q2;
    float e1 = tr - n1, e2 = td - n2;
    float b11 = n1 * (1.f - q1);
    float b22 = n2 * (1.f - q2);
    float b12 = -(n1 * q2);
    float detT = tt * n1 * q2 * (1.f - q1 - q2);
    float quadT = __fdividef(e1 * e1 * b22 - 2.f * e1 * e2 * b12 + e2 * e2 * b11, detT);

    float l = __logf(covE * detI * detT);
    return -0.5f * (5.f * LOG2PI + l + quadE + quadI + quadT);
}

__global__ void __launch_bounds__(256, 2) elem_EIT(
    const float* __restrict__ E,   const float* __restrict__ I,
    const float* __restrict__ T,
    const float* __restrict__ E_I, const float* __restrict__ I_T,
    const float* __restrict__ I_U, const float* __restrict__ T_R,
    const float* __restrict__ T_D,
    const float* __restrict__ detr, const float* __restrict__ recr,
    const float* __restrict__ pdE, const float* __restrict__ pdI,
    const float* __restrict__ pdT)
{
    const int r  = (blockIdx.x * blockDim.x + threadIdx.x) * 4;
    const int t0 = blockIdx.y * TCHUNK;
    int t1 = t0 + TCHUNK; if (t1 > TT) t1 = TT;

    float dE = __fdividef(1.f, 1.f + __expf(-pdE[0]));
    float dI = __fdividef(1.f, 1.f + __expf(-pdI[0]));
    float dT = __fdividef(1.f, 1.f + __expf(-pdT[0]));

    float a0 = 0.f, a1 = 0.f, a2 = 0.f, a3 = 0.f;
    for (int t = t0; t < t1; t++) {
        size_t idx = (size_t)t * R + r;
        float4 vE  = *(const float4*)(E + idx);
        float4 vI  = *(const float4*)(I + idx);
        float4 vT  = *(const float4*)(T + idx);
        float4 vei = *(const float4*)(E_I + idx);
        float4 vit = *(const float4*)(I_T + idx);
        float4 viu = *(const float4*)(I_U + idx);
        float4 vtr = *(const float4*)(T_R + idx);
        float4 vtd = *(const float4*)(T_D + idx);
        float4 vdt = *(const float4*)(detr + idx);
        float4 vrc = *(const float4*)(recr + idx);

        a0 += lp_eit(vE.x, vI.x, vT.x, vei.x, vit.x, viu.x, vtr.x, vtd.x, vdt.x, vrc.x, dE, dI, dT);
        a1 += lp_eit(vE.y, vI.y, vT.y, vei.y, vit.y, viu.y, vtr.y, vtd.y, vdt.y, vrc.y, dE, dI, dT);
        a2 += lp_eit(vE.z, vI.z, vT.z, vei.z, vit.z, viu.z, vtr.z, vtd.z, vdt.z, vrc.z, dE, dI, dT);
        a3 += lp_eit(vE.w, vI.w, vT.w, vei.w, vit.w, viu.w, vtr.w, vtd.w, vdt.w, vrc.w, dE, dI, dT);
    }
    *(float4*)&g_partialA[(size_t)blockIdx.y * R + r] = make_float4(a0, a1, a2, a3);
}

// S flow: needs AI (GEMM) and AN
__device__ __forceinline__ float lp_s(float s, float se, float con, float ai, float inv_an) {
    float z   = con * ai * inv_an;
    float pSE = 1.f - __expf(-z);
    float mS  = s * pSE;
    float covS = mS * (1.f - pSE);
    float dS  = se - mS;
    float quadS = __fdividef(dS * dS, covS);
    return -0.5f * (LOG2PI + __logf(covS) + quadS);
}

__global__ void __launch_bounds__(256) elem_S(
    const float* __restrict__ S, const float* __restrict__ S_E,
    const float* __restrict__ cont)
{
    const int r  = (blockIdx.x * blockDim.x + threadIdx.x) * 4;
    const int t0 = blockIdx.y * TCHUNK;
    int t1 = t0 + TCHUNK; if (t1 > TT) t1 = TT;

    float4 an = *(const float4*)&g_AN[r];
    float inv0 = __fdividef(1.f, an.x), inv1 = __fdividef(1.f, an.y);
    float inv2 = __fdividef(1.f, an.z), inv3 = __fdividef(1.f, an.w);

    float a0 = 0.f, a1 = 0.f, a2 = 0.f, a3 = 0.f;
    for (int t = t0; t < t1; t++) {
        size_t idx = (size_t)t * R + r;
        float4 vS  = *(const float4*)(S + idx);
        float4 vse = *(const float4*)(S_E + idx);
        float4 vcn = *(const float4*)(cont + idx);
        float4 vai = *(const float4*)(g_AI + idx);
        a0 += lp_s(vS.x, vse.x, vcn.x, vai.x, inv0);
        a1 += lp_s(vS.y, vse.y, vcn.y, vai.y, inv1);
        a2 += lp_s(vS.z, vse.z, vcn.z, vai.z, inv2);
        a3 += lp_s(vS.w, vse.w, vcn.w, vai.w, inv3);
    }
    *(float4*)&g_partialB[(size_t)blockIdx.y * R + r] = make_float4(a0, a1, a2, a3);
}

// ---------------- final deterministic reduce over chunks ----------------
__global__ void reduce_kernel(float* __restrict__ out) {
    int r = blockIdx.x * blockDim.x + threadIdx.x;
    float s = 0.f;
    #pragma unroll
    for (int c = 0; c < NCHUNKS; c++) s += g_partialA[c * R + r];
    #pragma unroll
    for (int c = 0; c < NCHUNKS; c++) s += g_partialB[c * R + r];
    out[r] = s;
}

// ---------------- launch ----------------
extern "C" void kernel_launch(void* const* d_in, const int* in_sizes, int n_in,
                              void* d_out, int out_size) {
    const float* S    = (const float*)d_in[0];
    const float* E    = (const float*)d_in[1];
    const float* I    = (const float*)d_in[2];
    const float* T    = (const float*)d_in[3];
    const float* N    = (const float*)d_in[4];
    const float* S_E  = (const float*)d_in[5];
    const float* E_I  = (const float*)d_in[6];
    const float* I_T  = (const float*)d_in[7];
    const float* I_U  = (const float*)d_in[8];
    const float* T_R  = (const float*)d_in[9];
    const float* T_D  = (const float*)d_in[10];
    const float* adj  = (const float*)d_in[11];
    const float* ldE  = (const float*)d_in[12];
    const float* ldI  = (const float*)d_in[13];
    const float* ldT  = (const float*)d_in[14];
    const float* detr = (const float*)d_in[15];
    const float* recr = (const float*)d_in[16];
    const float* cont = (const float*)d_in[17];
    float* out = (float*)d_out;

    float* AI;        cudaGetSymbolAddress((void**)&AI, g_AI);
    uint8_t* I8;      cudaGetSymbolAddress((void**)&I8, g_I8);
    uint8_t* ADJ8;    cudaGetSymbolAddress((void**)&ADJ8, g_ADJ8);

    cudaFuncSetAttribute(gemm_mma, cudaFuncAttributeMaxDynamicSharedMemorySize, GEMM_SMEM);

    static cudaStream_t s1 = nullptr;
    static cudaEvent_t evF = nullptr, evJ = nullptr;
    if (!s1) {
        cudaStreamCreateWithFlags(&s1, cudaStreamNonBlocking);
        cudaEventCreateWithFlags(&evF, cudaEventDisableTiming);
        cudaEventCreateWithFlags(&evJ, cudaEventDisableTiming);
    }

    // fork at t=0: elem_EIT overlaps the cvt phase (R8-proven overlap)
    cudaEventRecord(evF, 0);
    cudaStreamWaitEvent(s1, evF, 0);
    elem_EIT<<<dim3(R / 1024, NCHUNKS), 256, 0, s1>>>(
        E, I, T, E_I, I_T, I_U, T_R, T_D, detr, recr, ldE, ldI, ldT);

    // main chain: cvt -> fp8 gemm (64x64 tiles, 1024 CTAs) -> elem_S
    cvt_adj_an<<<R, 128>>>(adj, N, ADJ8);
    cvt_I8<<<512, 256>>>(I, I8, (int)((size_t)D * R / 8));
    gemm_mma<<<dim3(R / BN, D / BM), 128, GEMM_SMEM>>>(I8, ADJ8, AI);
    elem_S<<<dim3(R / 1024, NCHUNKS), 256>>>(S, S_E, cont);

    // join, then final reduce
    cudaEventRecord(evJ, s1);
    cudaStreamWaitEvent(0, evJ, 0);
    reduce_kernel<<<R / 128, 128>>>(out);
}

// round 15
// speedup vs baseline: 1.0233x; 1.0233x over previous
#include <cuda_runtime.h>
#include <cstdint>
#include <math.h>

// Problem constants (fixed by the reference: D=1024, R=4096)
#define D 1024
#define R 4096
#define TT (D - 1)
#define TCHUNK 8
#define NCHUNKS 128             // 128*8 = 1024 >= 1023

#define ISCALE    0.0078125f    // 2^-7 pre-scale of I into e4m3 range
#define ISCALE_INV 128.f

// ---------------- scratch (no allocation allowed) ----------------
__device__ float g_AI[(size_t)D * R];                 // 16 MB
__device__ float g_AN[R];
__device__ float g_partialA[NCHUNKS * R];             // EIT partials
__device__ float g_partialB[NCHUNKS * R];             // S partials
__device__ uint8_t g_I8[(size_t)D * R];               // 4 MB  (e4m3)
__device__ uint8_t g_ADJ8[(size_t)R * R];             // 16 MB (e4m3)

// ================= PTX helpers (sm_89-class max; no 'a'-gated features) ========
__device__ __forceinline__ uint32_t smem_u32(const void* p) {
    uint32_t a;
    asm("{ .reg .u64 t; cvta.to.shared.u64 t, %1; cvt.u32.u64 %0, t; }" : "=r"(a) : "l"(p));
    return a;
}

#define CPASYNC16(saddr, gaddr) \
    asm volatile("cp.async.cg.shared.global [%0], [%1], 16;" :: "r"(saddr), "l"(gaddr) : "memory")
#define CPASYNC_COMMIT() asm volatile("cp.async.commit_group;" ::: "memory")
#define CPASYNC_WAIT1()  asm volatile("cp.async.wait_group 1;" ::: "memory")

#define LDSM_X4(r0, r1, r2, r3, addr) \
    asm volatile("ldmatrix.sync.aligned.m8n8.x4.shared.b16 {%0,%1,%2,%3}, [%4];" \
                 : "=r"(r0), "=r"(r1), "=r"(r2), "=r"(r3) : "r"(addr))

#define MMA_FP8(c, a0, a1, a2, a3, b0, b1) \
    asm volatile("mma.sync.aligned.m16n8k32.row.col.f32.e4m3.e4m3.f32 " \
                 "{%0,%1,%2,%3}, {%4,%5,%6,%7}, {%8,%9}, {%0,%1,%2,%3};" \
                 : "+f"((c)[0]), "+f"((c)[1]), "+f"((c)[2]), "+f"((c)[3]) \
                 : "r"(a0), "r"(a1), "r"(a2), "r"(a3), "r"(b0), "r"(b1))

__device__ __forceinline__ uint32_t pack4_e4m3(float f0, float f1, float f2, float f3) {
    uint16_t lo, hi;
    asm("cvt.rn.satfinite.e4m3x2.f32 %0, %1, %2;" : "=h"(lo) : "f"(f1), "f"(f0));
    asm("cvt.rn.satfinite.e4m3x2.f32 %0, %1, %2;" : "=h"(hi) : "f"(f3), "f"(f2));
    return (uint32_t)lo | ((uint32_t)hi << 16);
}

// ---------------- fused adj: f32->e4m3 convert + AN[r] = adj[r,:] . N ----------
__global__ void __launch_bounds__(128) cvt_adj_an(
    const float* __restrict__ adj, const float* __restrict__ Nv,
    uint8_t* __restrict__ dst)
{
    __shared__ float wsum[4];
    const int r = blockIdx.x;
    const float* row = adj + (size_t)r * R;
    uint8_t* orow = dst + (size_t)r * R;

    float s = 0.f;
    #pragma unroll
    for (int it = 0; it < R / (128 * 8); it++) {
        int q = (it * 128 + threadIdx.x) * 8;
        float4 a = *(const float4*)(row + q);
        float4 b = *(const float4*)(row + q + 4);
        float4 n0 = *(const float4*)(Nv + q);
        float4 n1 = *(const float4*)(Nv + q + 4);
        uint2 o;
        o.x = pack4_e4m3(a.x, a.y, a.z, a.w);
        o.y = pack4_e4m3(b.x, b.y, b.z, b.w);
        *(uint2*)(orow + q) = o;
        s = fmaf(a.x, n0.x, s); s = fmaf(a.y, n0.y, s);
        s = fmaf(a.z, n0.z, s); s = fmaf(a.w, n0.w, s);
        s = fmaf(b.x, n1.x, s); s = fmaf(b.y, n1.y, s);
        s = fmaf(b.z, n1.z, s); s = fmaf(b.w, n1.w, s);
    }
    #pragma unroll
    for (int o = 16; o; o >>= 1) s += __shfl_down_sync(0xffffffffu, s, o);
    int lane = threadIdx.x & 31, wid = threadIdx.x >> 5;
    if (lane == 0) wsum[wid] = s;
    __syncthreads();
    if (threadIdx.x == 0)
        g_AN[r] = wsum[0] + wsum[1] + wsum[2] + wsum[3];
}

// ---------------- I: f32 -> e4m3 with 2^-7 scale ----------------
__global__ void cvt_I8(const float* __restrict__ src, uint8_t* __restrict__ dst, int n8) {
    int i = blockIdx.x * blockDim.x + threadIdx.x;
    int stride = gridDim.x * blockDim.x;
    for (; i < n8; i += stride) {
        float4 v0 = ((const float4*)src)[2 * i];
        float4 v1 = ((const float4*)src)[2 * i + 1];
        uint2 o;
        o.x = pack4_e4m3(v0.x * ISCALE, v0.y * ISCALE, v0.z * ISCALE, v0.w * ISCALE);
        o.y = pack4_e4m3(v1.x * ISCALE, v1.y * ISCALE, v1.z * ISCALE, v1.w * ISCALE);
        ((uint2*)dst)[i] = o;
    }
}

// ================= e4m3 GEMM: AI = 128 * I8 @ ADJ8^T =================
// 64x64 tiles, 128 threads (2x2 warps of 32x32), 1024 CTAs, 3-stage pipeline
// (48KB smem -> 4 CTAs/SM), single barrier per k-iter, LDSM addresses hoisted.
#define BM 64
#define BN 64
#define BK 128                  // e4m3 elements per chunk: 128 B per row
#define NKC (R / BK)            // 32 k-chunks
#define A_STG 8192              // 64 rows x 128 B
#define STG   16384             // A + B
#define GEMM_SMEM (3 * STG)     // 49152 B

__global__ void __launch_bounds__(128) gemm_mma(
    const uint8_t* __restrict__ A, const uint8_t* __restrict__ B,
    float* __restrict__ C)
{
    extern __shared__ char smem[];
    const uint32_t sbase = smem_u32(smem);
    const int tid  = threadIdx.x;
    const int lane = tid & 31;
    const int wid  = tid >> 5;
    const int bm = blockIdx.y * BM;
    const int bn = blockIdx.x * BN;

    // ---- producer: each of 128 threads loads 4 A segs + 4 B segs (16B each) ----
    uint64_t gpA[4], gpB[4];
    uint32_t soA[4], soB[4];
    #pragma unroll
    for (int j = 0; j < 4; j++) {
        int s = tid + j * 128;          // 0..511
        int row = s >> 3, pc = s & 7;
        gpA[j] = (uint64_t)(A + (size_t)(bm + row) * R + pc * 16);
        gpB[j] = (uint64_t)(B + (size_t)(bn + row) * R + pc * 16);
        soA[j] = (uint32_t)(row * 128 + ((pc ^ (row & 7)) << 4));
        soB[j] = soA[j] + A_STG;
    }

#define ISSUE_STAGE(kt, s)                                              \
    do {                                                                \
        uint32_t dst = sbase + (s) * STG;                               \
        _Pragma("unroll")                                               \
        for (int j = 0; j < 4; j++) {                                   \
            CPASYNC16(dst + soA[j], gpA[j] + (size_t)(kt) * BK);        \
            CPASYNC16(dst + soB[j], gpB[j] + (size_t)(kt) * BK);        \
        }                                                               \
    } while (0)

    // ---- consumer: 2x2 warps, each 32x32; hoist ALL ldsm addresses ----
    const int wm = (wid & 1) * 32;
    const int wn = (wid >> 1) * 32;
    const int l15 = lane & 15;
    const int lhi = lane >> 4;
    const int l7  = lane & 7;

    uint32_t offA[2][4], offB[2][4];
    #pragma unroll
    for (int kk = 0; kk < 4; kk++) {
        const uint32_t sw = (uint32_t)(((kk * 2 + lhi) ^ l7)) << 4;
        #pragma unroll
        for (int fm = 0; fm < 2; fm++)
            offA[fm][kk] = (uint32_t)(wm + fm * 16 + l15) * 128 + sw;
        #pragma unroll
        for (int nb = 0; nb < 2; nb++)
            offB[nb][kk] = (uint32_t)(wn + nb * 16 + l15) * 128 + A_STG + sw;
    }

    float c[2][4][4];
    #pragma unroll
    for (int fm = 0; fm < 2; fm++)
        #pragma unroll
        for (int nf = 0; nf < 4; nf++)
            #pragma unroll
            for (int v = 0; v < 4; v++) c[fm][nf][v] = 0.f;

    ISSUE_STAGE(0, 0); CPASYNC_COMMIT();
    ISSUE_STAGE(1, 1); CPASYNC_COMMIT();

    for (int kt = 0; kt < NKC; kt++) {
        const int s = kt % 3;
        CPASYNC_WAIT1();
        __syncthreads();   // stage-s visible AND all prev-iter reads done

        if (kt + 2 < NKC) { ISSUE_STAGE(kt + 2, (kt + 2) % 3); }
        CPASYNC_COMMIT();

        const uint32_t st = sbase + s * STG;
        #pragma unroll
        for (int kk = 0; kk < 4; kk++) {   // 4 x k32 per 128B chunk
            uint32_t a[2][4], bq[2][4];
            #pragma unroll
            for (int fm = 0; fm < 2; fm++)
                LDSM_X4(a[fm][0], a[fm][1], a[fm][2], a[fm][3], st + offA[fm][kk]);
            #pragma unroll
            for (int nb = 0; nb < 2; nb++)
                LDSM_X4(bq[nb][0], bq[nb][1], bq[nb][2], bq[nb][3], st + offB[nb][kk]);

            #pragma unroll
            for (int fm = 0; fm < 2; fm++)
                #pragma unroll
                for (int nf = 0; nf < 4; nf++) {
                    const int nb = nf >> 1, od = nf & 1;
                    MMA_FP8(c[fm][nf], a[fm][0], a[fm][1], a[fm][2], a[fm][3],
                            bq[nb][od], bq[nb][od + 2]);
                }
        }
        // no trailing barrier: next top barrier orders the stage rewrite
        // (prefetch into (kt+2)%3 == (kt-1)%3 happens only after the barrier)
    }

    // ---- epilogue (rescale by 2^7) ----
    const int g  = lane >> 2;
    const int t2 = (lane & 3) * 2;
    #pragma unroll
    for (int fm = 0; fm < 2; fm++) {
        float* p0 = C + (size_t)(bm + wm + fm * 16 + g) * R + bn + wn + t2;
        #pragma unroll
        for (int nf = 0; nf < 4; nf++) {
            *(float2*)(p0 + nf * 8) =
                make_float2(c[fm][nf][0] * ISCALE_INV, c[fm][nf][1] * ISCALE_INV);
            *(float2*)(p0 + 8 * R + nf * 8) =
                make_float2(c[fm][nf][2] * ISCALE_INV, c[fm][nf][3] * ISCALE_INV);
        }
    }
#undef ISSUE_STAGE
}

// ---------------- elementwise log-probs ----------------
#define LOG2PI 1.8378770664093454836f

__device__ __forceinline__ float lp_eit(
    float e, float i, float tt,
    float ei, float it, float iu, float tr, float td,
    float det, float rec, float dE, float dI, float dT)
{
    float mE  = e * dE;
    float covE = mE * (1.f - dE);
    float dEe = ei - mE;
    float quadE = __fdividef(dEe * dEe, covE);

    float p1 = det * dI, p2 = (1.f - det) * dI;
    float m1 = i * p1, m2 = i * p2;
    float d1 = it - m1, d2 = iu - m2;
    float c11 = m1 * (1.f - p1);
    float c22 = m2 * (1.f - p2);
    float c12 = -(m1 * p2);
    float detI = i * m1 * p2 * (1.f - p1 - p2);
    float quadI = __fdividef(d1 * d1 * c22 - 2.f * d1 * d2 * c12 + d2 * d2 * c11, detI);

    float q1 = rec * dT, q2 = (1.f - rec) * dT;
    float n1 = tt * q1, n2 = tt * q2;
    float e1 = tr - n1, e2 = td - n2;
    float b11 = n1 * (1.f - q1);
    float b22 = n2 * (1.f - q2);
    float b12 = -(n1 * q2);
    float detT = tt * n1 * q2 * (1.f - q1 - q2);
    float quadT = __fdividef(e1 * e1 * b22 - 2.f * e1 * e2 * b12 + e2 * e2 * b11, detT);

    float l = __logf(covE * detI * detT);
    return -0.5f * (5.f * LOG2PI + l + quadE + quadI + quadT);
}

__global__ void __launch_bounds__(256, 2) elem_EIT(
    const float* __restrict__ E,   const float* __restrict__ I,
    const float* __restrict__ T,
    const float* __restrict__ E_I, const float* __restrict__ I_T,
    const float* __restrict__ I_U, const float* __restrict__ T_R,
    const float* __restrict__ T_D,
    const float* __restrict__ detr, const float* __restrict__ recr,
    const float* __restrict__ pdE, const float* __restrict__ pdI,
    const float* __restrict__ pdT)
{
    const int r  = (blockIdx.x * blockDim.x + threadIdx.x) * 4;
    const int t0 = blockIdx.y * TCHUNK;
    int t1 = t0 + TCHUNK; if (t1 > TT) t1 = TT;

    float dE = __fdividef(1.f, 1.f + __expf(-pdE[0]));
    float dI = __fdividef(1.f, 1.f + __expf(-pdI[0]));
    float dT = __fdividef(1.f, 1.f + __expf(-pdT[0]));

    float a0 = 0.f, a1 = 0.f, a2 = 0.f, a3 = 0.f;
    for (int t = t0; t < t1; t++) {
        size_t idx = (size_t)t * R + r;
        float4 vE  = *(const float4*)(E + idx);
        float4 vI  = *(const float4*)(I + idx);
        float4 vT  = *(const float4*)(T + idx);
        float4 vei = *(const float4*)(E_I + idx);
        float4 vit = *(const float4*)(I_T + idx);
        float4 viu = *(const float4*)(I_U + idx);
        float4 vtr = *(const float4*)(T_R + idx);
        float4 vtd = *(const float4*)(T_D + idx);
        float4 vdt = *(const float4*)(detr + idx);
        float4 vrc = *(const float4*)(recr + idx);

        a0 += lp_eit(vE.x, vI.x, vT.x, vei.x, vit.x, viu.x, vtr.x, vtd.x, vdt.x, vrc.x, dE, dI, dT);
        a1 += lp_eit(vE.y, vI.y, vT.y, vei.y, vit.y, viu.y, vtr.y, vtd.y, vdt.y, vrc.y, dE, dI, dT);
        a2 += lp_eit(vE.z, vI.z, vT.z, vei.z, vit.z, viu.z, vtr.z, vtd.z, vdt.z, vrc.z, dE, dI, dT);
        a3 += lp_eit(vE.w, vI.w, vT.w, vei.w, vit.w, viu.w, vtr.w, vtd.w, vdt.w, vrc.w, dE, dI, dT);
    }
    *(float4*)&g_partialA[(size_t)blockIdx.y * R + r] = make_float4(a0, a1, a2, a3);
}

// S flow: needs AI (GEMM) and AN
__device__ __forceinline__ float lp_s(float s, float se, float con, float ai, float inv_an) {
    float z   = con * ai * inv_an;
    float pSE = 1.f - __expf(-z);
    float mS  = s * pSE;
    float covS = mS * (1.f - pSE);
    float dS  = se - mS;
    float quadS = __fdividef(dS * dS, covS);
    return -0.5f * (LOG2PI + __logf(covS) + quadS);
}

__global__ void __launch_bounds__(256) elem_S(
    const float* __restrict__ S, const float* __restrict__ S_E,
    const float* __restrict__ cont)
{
    const int r  = (blockIdx.x * blockDim.x + threadIdx.x) * 4;
    const int t0 = blockIdx.y * TCHUNK;
    int t1 = t0 + TCHUNK; if (t1 > TT) t1 = TT;

    float4 an = *(const float4*)&g_AN[r];
    float inv0 = __fdividef(1.f, an.x), inv1 = __fdividef(1.f, an.y);
    float inv2 = __fdividef(1.f, an.z), inv3 = __fdividef(1.f, an.w);

    float a0 = 0.f, a1 = 0.f, a2 = 0.f, a3 = 0.f;
    for (int t = t0; t < t1; t++) {
        size_t idx = (size_t)t * R + r;
        float4 vS  = *(const float4*)(S + idx);
        float4 vse = *(const float4*)(S_E + idx);
        float4 vcn = *(const float4*)(cont + idx);
        float4 vai = *(const float4*)(g_AI + idx);
        a0 += lp_s(vS.x, vse.x, vcn.x, vai.x, inv0);
        a1 += lp_s(vS.y, vse.y, vcn.y, vai.y, inv1);
        a2 += lp_s(vS.z, vse.z, vcn.z, vai.z, inv2);
        a3 += lp_s(vS.w, vse.w, vcn.w, vai.w, inv3);
    }
    *(float4*)&g_partialB[(size_t)blockIdx.y * R + r] = make_float4(a0, a1, a2, a3);
}

// ---------------- final deterministic reduce over chunks ----------------
__global__ void reduce_kernel(float* __restrict__ out) {
    int r = blockIdx.x * blockDim.x + threadIdx.x;
    float s = 0.f;
    #pragma unroll
    for (int c = 0; c < NCHUNKS; c++) s += g_partialA[c * R + r];
    #pragma unroll
    for (int c = 0; c < NCHUNKS; c++) s += g_partialB[c * R + r];
    out[r] = s;
}

// ---------------- launch ----------------
extern "C" void kernel_launch(void* const* d_in, const int* in_sizes, int n_in,
                              void* d_out, int out_size) {
    const float* S    = (const float*)d_in[0];
    const float* E    = (const float*)d_in[1];
    const float* I    = (const float*)d_in[2];
    const float* T    = (const float*)d_in[3];
    const float* N    = (const float*)d_in[4];
    const float* S_E  = (const float*)d_in[5];
    const float* E_I  = (const float*)d_in[6];
    const float* I_T  = (const float*)d_in[7];
    const float* I_U  = (const float*)d_in[8];
    const float* T_R  = (const float*)d_in[9];
    const float* T_D  = (const float*)d_in[10];
    const float* adj  = (const float*)d_in[11];
    const float* ldE  = (const float*)d_in[12];
    const float* ldI  = (const float*)d_in[13];
    const float* ldT  = (const float*)d_in[14];
    const float* detr = (const float*)d_in[15];
    const float* recr = (const float*)d_in[16];
    const float* cont = (const float*)d_in[17];
    float* out = (float*)d_out;

    float* AI;        cudaGetSymbolAddress((void**)&AI, g_AI);
    uint8_t* I8;      cudaGetSymbolAddress((void**)&I8, g_I8);
    uint8_t* ADJ8;    cudaGetSymbolAddress((void**)&ADJ8, g_ADJ8);

    cudaFuncSetAttribute(gemm_mma, cudaFuncAttributeMaxDynamicSharedMemorySize, GEMM_SMEM);

    static cudaStream_t s1 = nullptr;
    static cudaEvent_t evF = nullptr, evJ = nullptr;
    if (!s1) {
        cudaStreamCreateWithFlags(&s1, cudaStreamNonBlocking);
        cudaEventCreateWithFlags(&evF, cudaEventDisableTiming);
        cudaEventCreateWithFlags(&evJ, cudaEventDisableTiming);
    }

    // fork at t=0: elem_EIT overlaps the cvt phase (R8-proven overlap)
    cudaEventRecord(evF, 0);
    cudaStreamWaitEvent(s1, evF, 0);
    elem_EIT<<<dim3(R / 1024, NCHUNKS), 256, 0, s1>>>(
        E, I, T, E_I, I_T, I_U, T_R, T_D, detr, recr, ldE, ldI, ldT);

    // main chain: cvt -> fp8 gemm (64x64 tiles, 1024 CTAs) -> elem_S
    cvt_adj_an<<<R, 128>>>(adj, N, ADJ8);
    cvt_I8<<<512, 256>>>(I, I8, (int)((size_t)D * R / 8));
    gemm_mma<<<dim3(R / BN, D / BM), 128, GEMM_SMEM>>>(I8, ADJ8, AI);
    elem_S<<<dim3(R / 1024, NCHUNKS), 256>>>(S, S_E, cont);

    // join, then final reduce
    cudaEventRecord(evJ, s1);
    cudaStreamWaitEvent(0, evJ, 0);
    reduce_kernel<<<R / 128, 128>>>(out);
}

// round 16
// speedup vs baseline: 1.0427x; 1.0190x over previous
#include <cuda_runtime.h>
#include <cstdint>
#include <math.h>

// Problem constants (fixed by the reference: D=1024, R=4096)
#define D 1024
#define R 4096
#define TT (D - 1)
#define TCHUNK 8
#define NCHUNKS 128             // 128*8 = 1024 >= 1023

#define ISCALE    0.0078125f    // 2^-7 pre-scale of I into e4m3 range
#define ISCALE_INV 128.f

// ---------------- scratch (no allocation allowed) ----------------
__device__ float g_AI[(size_t)D * R];                 // 16 MB
__device__ float g_AN[R];
__device__ float g_partialA[NCHUNKS * R];             // EIT partials
__device__ float g_partialB[NCHUNKS * R];             // S partials
__device__ uint8_t g_I8[(size_t)D * R];               // 4 MB  (e4m3)
__device__ uint8_t g_ADJ8[(size_t)R * R];             // 16 MB (e4m3)

// ================= PTX helpers (sm_89-class max; no 'a'-gated features) ========
__device__ __forceinline__ uint32_t smem_u32(const void* p) {
    uint32_t a;
    asm("{ .reg .u64 t; cvta.to.shared.u64 t, %1; cvt.u32.u64 %0, t; }" : "=r"(a) : "l"(p));
    return a;
}

#define CPASYNC16(saddr, gaddr) \
    asm volatile("cp.async.cg.shared.global [%0], [%1], 16;" :: "r"(saddr), "l"(gaddr) : "memory")
#define CPASYNC_COMMIT() asm volatile("cp.async.commit_group;" ::: "memory")
#define CPASYNC_WAIT1()  asm volatile("cp.async.wait_group 1;" ::: "memory")

#define LDSM_X4(r0, r1, r2, r3, addr) \
    asm volatile("ldmatrix.sync.aligned.m8n8.x4.shared.b16 {%0,%1,%2,%3}, [%4];" \
                 : "=r"(r0), "=r"(r1), "=r"(r2), "=r"(r3) : "r"(addr))

#define MMA_FP8(c, a0, a1, a2, a3, b0, b1) \
    asm volatile("mma.sync.aligned.m16n8k32.row.col.f32.e4m3.e4m3.f32 " \
                 "{%0,%1,%2,%3}, {%4,%5,%6,%7}, {%8,%9}, {%0,%1,%2,%3};" \
                 : "+f"((c)[0]), "+f"((c)[1]), "+f"((c)[2]), "+f"((c)[3]) \
                 : "r"(a0), "r"(a1), "r"(a2), "r"(a3), "r"(b0), "r"(b1))

__device__ __forceinline__ uint32_t pack4_e4m3(float f0, float f1, float f2, float f3) {
    uint16_t lo, hi;
    asm("cvt.rn.satfinite.e4m3x2.f32 %0, %1, %2;" : "=h"(lo) : "f"(f1), "f"(f0));
    asm("cvt.rn.satfinite.e4m3x2.f32 %0, %1, %2;" : "=h"(hi) : "f"(f3), "f"(f2));
    return (uint32_t)lo | ((uint32_t)hi << 16);
}

#define LOG2PI 1.8378770664093454836f

// ---------------- fused adj: f32->e4m3 convert + AN[r] = adj[r,:] . N ----------
__global__ void __launch_bounds__(128) cvt_adj_an(
    const float* __restrict__ adj, const float* __restrict__ Nv,
    uint8_t* __restrict__ dst)
{
    __shared__ float wsum[4];
    const int r = blockIdx.x;
    const float* row = adj + (size_t)r * R;
    uint8_t* orow = dst + (size_t)r * R;

    float s = 0.f;
    #pragma unroll
    for (int it = 0; it < R / (128 * 8); it++) {
        int q = (it * 128 + threadIdx.x) * 8;
        float4 a = *(const float4*)(row + q);
        float4 b = *(const float4*)(row + q + 4);
        float4 n0 = *(const float4*)(Nv + q);
        float4 n1 = *(const float4*)(Nv + q + 4);
        uint2 o;
        o.x = pack4_e4m3(a.x, a.y, a.z, a.w);
        o.y = pack4_e4m3(b.x, b.y, b.z, b.w);
        *(uint2*)(orow + q) = o;
        s = fmaf(a.x, n0.x, s); s = fmaf(a.y, n0.y, s);
        s = fmaf(a.z, n0.z, s); s = fmaf(a.w, n0.w, s);
        s = fmaf(b.x, n1.x, s); s = fmaf(b.y, n1.y, s);
        s = fmaf(b.z, n1.z, s); s = fmaf(b.w, n1.w, s);
    }
    #pragma unroll
    for (int o = 16; o; o >>= 1) s += __shfl_down_sync(0xffffffffu, s, o);
    int lane = threadIdx.x & 31, wid = threadIdx.x >> 5;
    if (lane == 0) wsum[wid] = s;
    __syncthreads();
    if (threadIdx.x == 0)
        g_AN[r] = wsum[0] + wsum[1] + wsum[2] + wsum[3];
}

// ---------------- I: f32 -> e4m3 with 2^-7 scale ----------------
__global__ void cvt_I8(const float* __restrict__ src, uint8_t* __restrict__ dst, int n8) {
    int i = blockIdx.x * blockDim.x + threadIdx.x;
    int stride = gridDim.x * blockDim.x;
    for (; i < n8; i += stride) {
        float4 v0 = ((const float4*)src)[2 * i];
        float4 v1 = ((const float4*)src)[2 * i + 1];
        uint2 o;
        o.x = pack4_e4m3(v0.x * ISCALE, v0.y * ISCALE, v0.z * ISCALE, v0.w * ISCALE);
        o.y = pack4_e4m3(v1.x * ISCALE, v1.y * ISCALE, v1.z * ISCALE, v1.w * ISCALE);
        ((uint2*)dst)[i] = o;
    }
}

// ---------------- E/I/T log-prob (device fn used by merged kernel) ----------
__device__ __forceinline__ float lp_eit(
    float e, float i, float tt,
    float ei, float it, float iu, float tr, float td,
    float det, float rec, float dE, float dI, float dT)
{
    float mE  = e * dE;
    float covE = mE * (1.f - dE);
    float dEe = ei - mE;
    float quadE = __fdividef(dEe * dEe, covE);

    float p1 = det * dI, p2 = (1.f - det) * dI;
    float m1 = i * p1, m2 = i * p2;
    float d1 = it - m1, d2 = iu - m2;
    float c11 = m1 * (1.f - p1);
    float c22 = m2 * (1.f - p2);
    float c12 = -(m1 * p2);
    float detI = i * m1 * p2 * (1.f - p1 - p2);
    float quadI = __fdividef(d1 * d1 * c22 - 2.f * d1 * d2 * c12 + d2 * d2 * c11, detI);

    float q1 = rec * dT, q2 = (1.f - rec) * dT;
    float n1 = tt * q1, n2 = tt * q2;
    float e1 = tr - n1, e2 = td - n2;
    float b11 = n1 * (1.f - q1);
    float b22 = n2 * (1.f - q2);
    float b12 = -(n1 * q2);
    float detT = tt * n1 * q2 * (1.f - q1 - q2);
    float quadT = __fdividef(e1 * e1 * b22 - 2.f * e1 * e2 * b12 + e2 * e2 * b11, detT);

    float l = __logf(covE * detI * detT);
    return -0.5f * (5.f * LOG2PI + l + quadE + quadI + quadT);
}

// ========== MERGED kernel: even CTAs = fp8 GEMM tile, odd CTAs = EIT block =====
// GEMM: 64x64 tiles, 4 warps of 32x32, 3-stage cp.async pipeline (48KB).
// EIT: 128 threads x 4 r's x 8 t's. Interleaving on each SM hides EIT's DRAM
// work under the GEMM's tensor work (stream co-scheduling never did).
#define BM 64
#define BN 64
#define BK 128
#define NKC (R / BK)            // 32 k-chunks
#define A_STG 8192
#define STG   16384
#define GEMM_SMEM (3 * STG)     // 49152 B

__global__ void __launch_bounds__(128) gemm_eit(
    const uint8_t* __restrict__ A, const uint8_t* __restrict__ B,
    float* __restrict__ C,
    const float* __restrict__ E,   const float* __restrict__ I,
    const float* __restrict__ T,
    const float* __restrict__ E_I, const float* __restrict__ I_T,
    const float* __restrict__ I_U, const float* __restrict__ T_R,
    const float* __restrict__ T_D,
    const float* __restrict__ detr, const float* __restrict__ recr,
    const float* __restrict__ pdE, const float* __restrict__ pdI,
    const float* __restrict__ pdT)
{
    const int tid = threadIdx.x;

    if (blockIdx.x & 1) {
        // ================= EIT branch =================
        const int bid = blockIdx.x >> 1;          // 0..1023
        const int r  = ((bid & 7) * 128 + tid) * 4;
        const int t0 = (bid >> 3) * TCHUNK;
        int t1 = t0 + TCHUNK; if (t1 > TT) t1 = TT;

        float dE = __fdividef(1.f, 1.f + __expf(-pdE[0]));
        float dI = __fdividef(1.f, 1.f + __expf(-pdI[0]));
        float dT = __fdividef(1.f, 1.f + __expf(-pdT[0]));

        float a0 = 0.f, a1 = 0.f, a2 = 0.f, a3 = 0.f;
        for (int t = t0; t < t1; t++) {
            size_t idx = (size_t)t * R + r;
            float4 vE  = *(const float4*)(E + idx);
            float4 vI  = *(const float4*)(I + idx);
            float4 vT  = *(const float4*)(T + idx);
            float4 vei = *(const float4*)(E_I + idx);
            float4 vit = *(const float4*)(I_T + idx);
            float4 viu = *(const float4*)(I_U + idx);
            float4 vtr = *(const float4*)(T_R + idx);
            float4 vtd = *(const float4*)(T_D + idx);
            float4 vdt = *(const float4*)(detr + idx);
            float4 vrc = *(const float4*)(recr + idx);

            a0 += lp_eit(vE.x, vI.x, vT.x, vei.x, vit.x, viu.x, vtr.x, vtd.x, vdt.x, vrc.x, dE, dI, dT);
            a1 += lp_eit(vE.y, vI.y, vT.y, vei.y, vit.y, viu.y, vtr.y, vtd.y, vdt.y, vrc.y, dE, dI, dT);
            a2 += lp_eit(vE.z, vI.z, vT.z, vei.z, vit.z, viu.z, vtr.z, vtd.z, vdt.z, vrc.z, dE, dI, dT);
            a3 += lp_eit(vE.w, vI.w, vT.w, vei.w, vit.w, viu.w, vtr.w, vtd.w, vdt.w, vrc.w, dE, dI, dT);
        }
        *(float4*)&g_partialA[(size_t)(bid >> 3) * R + r] = make_float4(a0, a1, a2, a3);
        return;
    }

    // ================= GEMM branch =================
    extern __shared__ char smem[];
    const uint32_t sbase = smem_u32(smem);
    const int lane = tid & 31;
    const int wid  = tid >> 5;
    const int bid  = blockIdx.x >> 1;             // 0..1023
    const int bm = (bid >> 6) * BM;               // 16 m-tiles
    const int bn = (bid & 63) * BN;               // 64 n-tiles

    uint64_t gpA[4], gpB[4];
    uint32_t soA[4], soB[4];
    #pragma unroll
    for (int j = 0; j < 4; j++) {
        int s = tid + j * 128;
        int row = s >> 3, pc = s & 7;
        gpA[j] = (uint64_t)(A + (size_t)(bm + row) * R + pc * 16);
        gpB[j] = (uint64_t)(B + (size_t)(bn + row) * R + pc * 16);
        soA[j] = (uint32_t)(row * 128 + ((pc ^ (row & 7)) << 4));
        soB[j] = soA[j] + A_STG;
    }

#define ISSUE_STAGE(kt, s)                                              \
    do {                                                                \
        uint32_t dst = sbase + (s) * STG;                               \
        _Pragma("unroll")                                               \
        for (int j = 0; j < 4; j++) {                                   \
            CPASYNC16(dst + soA[j], gpA[j] + (size_t)(kt) * BK);        \
            CPASYNC16(dst + soB[j], gpB[j] + (size_t)(kt) * BK);        \
        }                                                               \
    } while (0)

    const int wm = (wid & 1) * 32;
    const int wn = (wid >> 1) * 32;
    const int l15 = lane & 15;
    const int lhi = lane >> 4;
    const int l7  = lane & 7;

    uint32_t offA[2][4], offB[2][4];
    #pragma unroll
    for (int kk = 0; kk < 4; kk++) {
        const uint32_t sw = (uint32_t)(((kk * 2 + lhi) ^ l7)) << 4;
        #pragma unroll
        for (int fm = 0; fm < 2; fm++)
            offA[fm][kk] = (uint32_t)(wm + fm * 16 + l15) * 128 + sw;
        #pragma unroll
        for (int nb = 0; nb < 2; nb++)
            offB[nb][kk] = (uint32_t)(wn + nb * 16 + l15) * 128 + A_STG + sw;
    }

    float c[2][4][4];
    #pragma unroll
    for (int fm = 0; fm < 2; fm++)
        #pragma unroll
        for (int nf = 0; nf < 4; nf++)
            #pragma unroll
            for (int v = 0; v < 4; v++) c[fm][nf][v] = 0.f;

    ISSUE_STAGE(0, 0); CPASYNC_COMMIT();
    ISSUE_STAGE(1, 1); CPASYNC_COMMIT();

    for (int kt = 0; kt < NKC; kt++) {
        const int s = kt % 3;
        CPASYNC_WAIT1();
        __syncthreads();

        if (kt + 2 < NKC) { ISSUE_STAGE(kt + 2, (kt + 2) % 3); }
        CPASYNC_COMMIT();

        const uint32_t st = sbase + s * STG;
        #pragma unroll
        for (int kk = 0; kk < 4; kk++) {
            uint32_t a[2][4], bq[2][4];
            #pragma unroll
            for (int fm = 0; fm < 2; fm++)
                LDSM_X4(a[fm][0], a[fm][1], a[fm][2], a[fm][3], st + offA[fm][kk]);
            #pragma unroll
            for (int nb = 0; nb < 2; nb++)
                LDSM_X4(bq[nb][0], bq[nb][1], bq[nb][2], bq[nb][3], st + offB[nb][kk]);

            #pragma unroll
            for (int fm = 0; fm < 2; fm++)
                #pragma unroll
                for (int nf = 0; nf < 4; nf++) {
                    const int nb = nf >> 1, od = nf & 1;
                    MMA_FP8(c[fm][nf], a[fm][0], a[fm][1], a[fm][2], a[fm][3],
                            bq[nb][od], bq[nb][od + 2]);
                }
        }
    }

    const int g  = lane >> 2;
    const int t2 = (lane & 3) * 2;
    #pragma unroll
    for (int fm = 0; fm < 2; fm++) {
        float* p0 = C + (size_t)(bm + wm + fm * 16 + g) * R + bn + wn + t2;
        #pragma unroll
        for (int nf = 0; nf < 4; nf++) {
            *(float2*)(p0 + nf * 8) =
                make_float2(c[fm][nf][0] * ISCALE_INV, c[fm][nf][1] * ISCALE_INV);
            *(float2*)(p0 + 8 * R + nf * 8) =
                make_float2(c[fm][nf][2] * ISCALE_INV, c[fm][nf][3] * ISCALE_INV);
        }
    }
#undef ISSUE_STAGE
}

// ---------------- S flow (needs AI + AN) ----------------
__device__ __forceinline__ float lp_s(float s, float se, float con, float ai, float inv_an) {
    float z   = con * ai * inv_an;
    float pSE = 1.f - __expf(-z);
    float mS  = s * pSE;
    float covS = mS * (1.f - pSE);
    float dS  = se - mS;
    float quadS = __fdividef(dS * dS, covS);
    return -0.5f * (LOG2PI + __logf(covS) + quadS);
}

__global__ void __launch_bounds__(256) elem_S(
    const float* __restrict__ S, const float* __restrict__ S_E,
    const float* __restrict__ cont)
{
    const int r  = (blockIdx.x * blockDim.x + threadIdx.x) * 4;
    const int t0 = blockIdx.y * TCHUNK;
    int t1 = t0 + TCHUNK; if (t1 > TT) t1 = TT;

    float4 an = *(const float4*)&g_AN[r];
    float inv0 = __fdividef(1.f, an.x), inv1 = __fdividef(1.f, an.y);
    float inv2 = __fdividef(1.f, an.z), inv3 = __fdividef(1.f, an.w);

    float a0 = 0.f, a1 = 0.f, a2 = 0.f, a3 = 0.f;
    for (int t = t0; t < t1; t++) {
        size_t idx = (size_t)t * R + r;
        float4 vS  = *(const float4*)(S + idx);
        float4 vse = *(const float4*)(S_E + idx);
        float4 vcn = *(const float4*)(cont + idx);
        float4 vai = *(const float4*)(g_AI + idx);
        a0 += lp_s(vS.x, vse.x, vcn.x, vai.x, inv0);
        a1 += lp_s(vS.y, vse.y, vcn.y, vai.y, inv1);
        a2 += lp_s(vS.z, vse.z, vcn.z, vai.z, inv2);
        a3 += lp_s(vS.w, vse.w, vcn.w, vai.w, inv3);
    }
    *(float4*)&g_partialB[(size_t)blockIdx.y * R + r] = make_float4(a0, a1, a2, a3);
}

// ---------------- final deterministic reduce over chunks ----------------
__global__ void reduce_kernel(float* __restrict__ out) {
    int r = blockIdx.x * blockDim.x + threadIdx.x;
    float s = 0.f;
    #pragma unroll
    for (int c = 0; c < NCHUNKS; c++) s += g_partialA[c * R + r];
    #pragma unroll
    for (int c = 0; c < NCHUNKS; c++) s += g_partialB[c * R + r];
    out[r] = s;
}

// ---------------- launch ----------------
extern "C" void kernel_launch(void* const* d_in, const int* in_sizes, int n_in,
                              void* d_out, int out_size) {
    const float* S    = (const float*)d_in[0];
    const float* E    = (const float*)d_in[1];
    const float* I    = (const float*)d_in[2];
    const float* T    = (const float*)d_in[3];
    const float* N    = (const float*)d_in[4];
    const float* S_E  = (const float*)d_in[5];
    const float* E_I  = (const float*)d_in[6];
    const float* I_T  = (const float*)d_in[7];
    const float* I_U  = (const float*)d_in[8];
    const float* T_R  = (const float*)d_in[9];
    const float* T_D  = (const float*)d_in[10];
    const float* adj  = (const float*)d_in[11];
    const float* ldE  = (const float*)d_in[12];
    const float* ldI  = (const float*)d_in[13];
    const float* ldT  = (const float*)d_in[14];
    const float* detr = (const float*)d_in[15];
    const float* recr = (const float*)d_in[16];
    const float* cont = (const float*)d_in[17];
    float* out = (float*)d_out;

    float* AI;        cudaGetSymbolAddress((void**)&AI, g_AI);
    uint8_t* I8;      cudaGetSymbolAddress((void**)&I8, g_I8);
    uint8_t* ADJ8;    cudaGetSymbolAddress((void**)&ADJ8, g_ADJ8);

    cudaFuncSetAttribute(gemm_eit, cudaFuncAttributeMaxDynamicSharedMemorySize, GEMM_SMEM);

    // 1) cvt phase (DRAM-bound, feeds the GEMM)
    cvt_adj_an<<<R, 128>>>(adj, N, ADJ8);
    cvt_I8<<<512, 256>>>(I, I8, (int)((size_t)D * R / 8));

    // 2) merged GEMM + EIT: guaranteed SM-level interleaving (2048 mixed CTAs)
    gemm_eit<<<2048, 128, GEMM_SMEM>>>(
        I8, ADJ8, AI,
        E, I, T, E_I, I_T, I_U, T_R, T_D, detr, recr, ldE, ldI, ldT);

    // 3) S flow (needs AI), then final reduce
    elem_S<<<dim3(R / 1024, NCHUNKS), 256>>>(S, S_E, cont);
    reduce_kernel<<<R / 128, 128>>>(out);
}

// round 17
// speedup vs baseline: 1.0811x; 1.0369x over previous
#include <cuda_runtime.h>
#include <cstdint>
#include <math.h>

// Problem constants (fixed by the reference: D=1024, R=4096)
#define D 1024
#define R 4096
#define TT (D - 1)
#define TCHUNK 8
#define NCHUNKS 128             // 128*8 = 1024 >= 1023

#define ISCALE    0.0078125f    // 2^-7 pre-scale of I into e4m3 range
#define ISCALE_INV 128.f

// ---------------- scratch (no allocation allowed) ----------------
__device__ float g_AN[R];
__device__ float g_partialA[NCHUNKS * R];             // EIT partials
__device__ float g_partialB[16 * R];                  // S partials (16 m-tiles)
__device__ uint8_t g_I8[(size_t)D * R];               // 4 MB  (e4m3)
__device__ uint8_t g_ADJ8[(size_t)R * R];             // 16 MB (e4m3)

// ================= PTX helpers (sm_89-class max; no 'a'-gated features) ========
__device__ __forceinline__ uint32_t smem_u32(const void* p) {
    uint32_t a;
    asm("{ .reg .u64 t; cvta.to.shared.u64 t, %1; cvt.u32.u64 %0, t; }" : "=r"(a) : "l"(p));
    return a;
}

#define CPASYNC16(saddr, gaddr) \
    asm volatile("cp.async.cg.shared.global [%0], [%1], 16;" :: "r"(saddr), "l"(gaddr) : "memory")
#define CPASYNC_COMMIT() asm volatile("cp.async.commit_group;" ::: "memory")
#define CPASYNC_WAIT1()  asm volatile("cp.async.wait_group 1;" ::: "memory")

#define LDSM_X4(r0, r1, r2, r3, addr) \
    asm volatile("ldmatrix.sync.aligned.m8n8.x4.shared.b16 {%0,%1,%2,%3}, [%4];" \
                 : "=r"(r0), "=r"(r1), "=r"(r2), "=r"(r3) : "r"(addr))

#define MMA_FP8(c, a0, a1, a2, a3, b0, b1) \
    asm volatile("mma.sync.aligned.m16n8k32.row.col.f32.e4m3.e4m3.f32 " \
                 "{%0,%1,%2,%3}, {%4,%5,%6,%7}, {%8,%9}, {%0,%1,%2,%3};" \
                 : "+f"((c)[0]), "+f"((c)[1]), "+f"((c)[2]), "+f"((c)[3]) \
                 : "r"(a0), "r"(a1), "r"(a2), "r"(a3), "r"(b0), "r"(b1))

__device__ __forceinline__ uint32_t pack4_e4m3(float f0, float f1, float f2, float f3) {
    uint16_t lo, hi;
    asm("cvt.rn.satfinite.e4m3x2.f32 %0, %1, %2;" : "=h"(lo) : "f"(f1), "f"(f0));
    asm("cvt.rn.satfinite.e4m3x2.f32 %0, %1, %2;" : "=h"(hi) : "f"(f3), "f"(f2));
    return (uint32_t)lo | ((uint32_t)hi << 16);
}

#define LOG2PI 1.8378770664093454836f

// S flow: 1-D Gaussian log-pdf with binomial mean/var from contagion
__device__ __forceinline__ float lp_s(float s, float se, float con, float ai, float inv_an) {
    float z   = con * ai * inv_an;
    float pSE = 1.f - __expf(-z);
    float mS  = s * pSE;
    float covS = mS * (1.f - pSE);
    float dS  = se - mS;
    float quadS = __fdividef(dS * dS, covS);
    return -0.5f * (LOG2PI + __logf(covS) + quadS);
}

// ---------------- fused adj: f32->e4m3 convert + AN[r] = adj[r,:] . N ----------
__global__ void __launch_bounds__(128) cvt_adj_an(
    const float* __restrict__ adj, const float* __restrict__ Nv,
    uint8_t* __restrict__ dst)
{
    __shared__ float wsum[4];
    const int r = blockIdx.x;
    const float* row = adj + (size_t)r * R;
    uint8_t* orow = dst + (size_t)r * R;

    float s = 0.f;
    #pragma unroll
    for (int it = 0; it < R / (128 * 8); it++) {
        int q = (it * 128 + threadIdx.x) * 8;
        float4 a = *(const float4*)(row + q);
        float4 b = *(const float4*)(row + q + 4);
        float4 n0 = *(const float4*)(Nv + q);
        float4 n1 = *(const float4*)(Nv + q + 4);
        uint2 o;
        o.x = pack4_e4m3(a.x, a.y, a.z, a.w);
        o.y = pack4_e4m3(b.x, b.y, b.z, b.w);
        *(uint2*)(orow + q) = o;
        s = fmaf(a.x, n0.x, s); s = fmaf(a.y, n0.y, s);
        s = fmaf(a.z, n0.z, s); s = fmaf(a.w, n0.w, s);
        s = fmaf(b.x, n1.x, s); s = fmaf(b.y, n1.y, s);
        s = fmaf(b.z, n1.z, s); s = fmaf(b.w, n1.w, s);
    }
    #pragma unroll
    for (int o = 16; o; o >>= 1) s += __shfl_down_sync(0xffffffffu, s, o);
    int lane = threadIdx.x & 31, wid = threadIdx.x >> 5;
    if (lane == 0) wsum[wid] = s;
    __syncthreads();
    if (threadIdx.x == 0)
        g_AN[r] = wsum[0] + wsum[1] + wsum[2] + wsum[3];
}

// ---------------- I: f32 -> e4m3 with 2^-7 scale ----------------
__global__ void cvt_I8(const float* __restrict__ src, uint8_t* __restrict__ dst, int n8) {
    int i = blockIdx.x * blockDim.x + threadIdx.x;
    int stride = gridDim.x * blockDim.x;
    for (; i < n8; i += stride) {
        float4 v0 = ((const float4*)src)[2 * i];
        float4 v1 = ((const float4*)src)[2 * i + 1];
        uint2 o;
        o.x = pack4_e4m3(v0.x * ISCALE, v0.y * ISCALE, v0.z * ISCALE, v0.w * ISCALE);
        o.y = pack4_e4m3(v1.x * ISCALE, v1.y * ISCALE, v1.z * ISCALE, v1.w * ISCALE);
        ((uint2*)dst)[i] = o;
    }
}

// ---------------- E/I/T log-prob ----------------
__device__ __forceinline__ float lp_eit(
    float e, float i, float tt,
    float ei, float it, float iu, float tr, float td,
    float det, float rec, float dE, float dI, float dT)
{
    float mE  = e * dE;
    float covE = mE * (1.f - dE);
    float dEe = ei - mE;
    float quadE = __fdividef(dEe * dEe, covE);

    float p1 = det * dI, p2 = (1.f - det) * dI;
    float m1 = i * p1, m2 = i * p2;
    float d1 = it - m1, d2 = iu - m2;
    float c11 = m1 * (1.f - p1);
    float c22 = m2 * (1.f - p2);
    float c12 = -(m1 * p2);
    float detI = i * m1 * p2 * (1.f - p1 - p2);
    float quadI = __fdividef(d1 * d1 * c22 - 2.f * d1 * d2 * c12 + d2 * d2 * c11, detI);

    float q1 = rec * dT, q2 = (1.f - rec) * dT;
    float n1 = tt * q1, n2 = tt * q2;
    float e1 = tr - n1, e2 = td - n2;
    float b11 = n1 * (1.f - q1);
    float b22 = n2 * (1.f - q2);
    float b12 = -(n1 * q2);
    float detT = tt * n1 * q2 * (1.f - q1 - q2);
    float quadT = __fdividef(e1 * e1 * b22 - 2.f * e1 * e2 * b12 + e2 * e2 * b11, detT);

    float l = __logf(covE * detI * detT);
    return -0.5f * (5.f * LOG2PI + l + quadE + quadI + quadT);
}

// ========== MERGED kernel: even CTAs = fp8 GEMM tile + fused S epilogue,
//            odd CTAs = EIT block. AI never touches DRAM. ==========
#define BM 64
#define BN 64
#define BK 128
#define NKC (R / BK)            // 32 k-chunks
#define A_STG 8192
#define STG   16384
#define GEMM_SMEM (3 * STG)     // 49152 B

__global__ void __launch_bounds__(128) gemm_eit(
    const uint8_t* __restrict__ A, const uint8_t* __restrict__ B,
    const float* __restrict__ S,   const float* __restrict__ S_E,
    const float* __restrict__ cont,
    const float* __restrict__ E,   const float* __restrict__ I,
    const float* __restrict__ T,
    const float* __restrict__ E_I, const float* __restrict__ I_T,
    const float* __restrict__ I_U, const float* __restrict__ T_R,
    const float* __restrict__ T_D,
    const float* __restrict__ detr, const float* __restrict__ recr,
    const float* __restrict__ pdE, const float* __restrict__ pdI,
    const float* __restrict__ pdT)
{
    const int tid = threadIdx.x;

    if (blockIdx.x & 1) {
        // ================= EIT branch =================
        const int bid = blockIdx.x >> 1;          // 0..1023
        const int r  = ((bid & 7) * 128 + tid) * 4;
        const int t0 = (bid >> 3) * TCHUNK;
        int t1 = t0 + TCHUNK; if (t1 > TT) t1 = TT;

        float dE = __fdividef(1.f, 1.f + __expf(-pdE[0]));
        float dI = __fdividef(1.f, 1.f + __expf(-pdI[0]));
        float dT = __fdividef(1.f, 1.f + __expf(-pdT[0]));

        float a0 = 0.f, a1 = 0.f, a2 = 0.f, a3 = 0.f;
        for (int t = t0; t < t1; t++) {
            size_t idx = (size_t)t * R + r;
            float4 vE  = *(const float4*)(E + idx);
            float4 vI  = *(const float4*)(I + idx);
            float4 vT  = *(const float4*)(T + idx);
            float4 vei = *(const float4*)(E_I + idx);
            float4 vit = *(const float4*)(I_T + idx);
            float4 viu = *(const float4*)(I_U + idx);
            float4 vtr = *(const float4*)(T_R + idx);
            float4 vtd = *(const float4*)(T_D + idx);
            float4 vdt = *(const float4*)(detr + idx);
            float4 vrc = *(const float4*)(recr + idx);

            a0 += lp_eit(vE.x, vI.x, vT.x, vei.x, vit.x, viu.x, vtr.x, vtd.x, vdt.x, vrc.x, dE, dI, dT);
            a1 += lp_eit(vE.y, vI.y, vT.y, vei.y, vit.y, viu.y, vtr.y, vtd.y, vdt.y, vrc.y, dE, dI, dT);
            a2 += lp_eit(vE.z, vI.z, vT.z, vei.z, vit.z, viu.z, vtr.z, vtd.z, vdt.z, vrc.z, dE, dI, dT);
            a3 += lp_eit(vE.w, vI.w, vT.w, vei.w, vit.w, viu.w, vtr.w, vtd.w, vdt.w, vrc.w, dE, dI, dT);
        }
        *(float4*)&g_partialA[(size_t)(bid >> 3) * R + r] = make_float4(a0, a1, a2, a3);
        return;
    }

    // ================= GEMM branch =================
    extern __shared__ char smem[];
    const uint32_t sbase = smem_u32(smem);
    const int lane = tid & 31;
    const int wid  = tid >> 5;
    const int bid  = blockIdx.x >> 1;             // 0..1023
    const int bm = (bid >> 6) * BM;               // 16 m-tiles
    const int bn = (bid & 63) * BN;               // 64 n-tiles

    uint64_t gpA[4], gpB[4];
    uint32_t soA[4], soB[4];
    #pragma unroll
    for (int j = 0; j < 4; j++) {
        int s = tid + j * 128;
        int row = s >> 3, pc = s & 7;
        gpA[j] = (uint64_t)(A + (size_t)(bm + row) * R + pc * 16);
        gpB[j] = (uint64_t)(B + (size_t)(bn + row) * R + pc * 16);
        soA[j] = (uint32_t)(row * 128 + ((pc ^ (row & 7)) << 4));
        soB[j] = soA[j] + A_STG;
    }

#define ISSUE_STAGE(kt, s)                                              \
    do {                                                                \
        uint32_t dst = sbase + (s) * STG;                               \
        _Pragma("unroll")                                               \
        for (int j = 0; j < 4; j++) {                                   \
            CPASYNC16(dst + soA[j], gpA[j] + (size_t)(kt) * BK);        \
            CPASYNC16(dst + soB[j], gpB[j] + (size_t)(kt) * BK);        \
        }                                                               \
    } while (0)

    const int wm = (wid & 1) * 32;
    const int wn = (wid >> 1) * 32;
    const int l15 = lane & 15;
    const int lhi = lane >> 4;
    const int l7  = lane & 7;

    uint32_t offA[2][4], offB[2][4];
    #pragma unroll
    for (int kk = 0; kk < 4; kk++) {
        const uint32_t sw = (uint32_t)(((kk * 2 + lhi) ^ l7)) << 4;
        #pragma unroll
        for (int fm = 0; fm < 2; fm++)
            offA[fm][kk] = (uint32_t)(wm + fm * 16 + l15) * 128 + sw;
        #pragma unroll
        for (int nb = 0; nb < 2; nb++)
            offB[nb][kk] = (uint32_t)(wn + nb * 16 + l15) * 128 + A_STG + sw;
    }

    float c[2][4][4];
    #pragma unroll
    for (int fm = 0; fm < 2; fm++)
        #pragma unroll
        for (int nf = 0; nf < 4; nf++)
            #pragma unroll
            for (int v = 0; v < 4; v++) c[fm][nf][v] = 0.f;

    ISSUE_STAGE(0, 0); CPASYNC_COMMIT();
    ISSUE_STAGE(1, 1); CPASYNC_COMMIT();

    for (int kt = 0; kt < NKC; kt++) {
        const int s = kt % 3;
        CPASYNC_WAIT1();
        __syncthreads();

        if (kt + 2 < NKC) { ISSUE_STAGE(kt + 2, (kt + 2) % 3); }
        CPASYNC_COMMIT();

        const uint32_t st = sbase + s * STG;
        #pragma unroll
        for (int kk = 0; kk < 4; kk++) {
            uint32_t a[2][4], bq[2][4];
            #pragma unroll
            for (int fm = 0; fm < 2; fm++)
                LDSM_X4(a[fm][0], a[fm][1], a[fm][2], a[fm][3], st + offA[fm][kk]);
            #pragma unroll
            for (int nb = 0; nb < 2; nb++)
                LDSM_X4(bq[nb][0], bq[nb][1], bq[nb][2], bq[nb][3], st + offB[nb][kk]);

            #pragma unroll
            for (int fm = 0; fm < 2; fm++)
                #pragma unroll
                for (int nf = 0; nf < 4; nf++) {
                    const int nb = nf >> 1, od = nf & 1;
                    MMA_FP8(c[fm][nf], a[fm][0], a[fm][1], a[fm][2], a[fm][3],
                            bq[nb][od], bq[nb][od + 2]);
                }
        }
    }

    // ================= fused S-flow epilogue (AI stays in registers) ==========
    __syncthreads();   // pipeline smem is dead; reuse for the reduction

    const int g  = lane >> 2;
    const int t2 = (lane & 3) * 2;

    float colsum[4][2];
    #pragma unroll
    for (int nf = 0; nf < 4; nf++) {
        const int r = bn + wn + nf * 8 + t2;
        float2 an2 = *(const float2*)&g_AN[r];
        float inv0 = __fdividef(1.f, an2.x);
        float inv1 = __fdividef(1.f, an2.y);
        float s0 = 0.f, s1 = 0.f;
        #pragma unroll
        for (int fm = 0; fm < 2; fm++) {
            #pragma unroll
            for (int h = 0; h < 2; h++) {
                const int t = bm + wm + fm * 16 + g + h * 8;
                if (t < TT) {
                    size_t idx = (size_t)t * R + r;
                    float2 sv = *(const float2*)(S + idx);
                    float2 se = *(const float2*)(S_E + idx);
                    float2 cn = *(const float2*)(cont + idx);
                    s0 += lp_s(sv.x, se.x, cn.x, c[fm][nf][h * 2 + 0] * ISCALE_INV, inv0);
                    s1 += lp_s(sv.y, se.y, cn.y, c[fm][nf][h * 2 + 1] * ISCALE_INV, inv1);
                }
            }
        }
        // reduce over g (lane bits 2..4): all 32 m-rows of this warp
        #pragma unroll
        for (int off = 4; off <= 16; off <<= 1) {
            s0 += __shfl_xor_sync(0xffffffffu, s0, off);
            s1 += __shfl_xor_sync(0xffffffffu, s1, off);
        }
        colsum[nf][0] = s0;
        colsum[nf][1] = s1;
    }

    float* sred = (float*)smem;   // 4 warps x 32 columns
    if (lane < 4) {
        #pragma unroll
        for (int nf = 0; nf < 4; nf++) {
            sred[wid * 32 + nf * 8 + t2]     = colsum[nf][0];
            sred[wid * 32 + nf * 8 + t2 + 1] = colsum[nf][1];
        }
    }
    __syncthreads();

    // combine the 2 M-warps within each N-half; write per-(m_tile, r) partial
    if (tid < 64) {
        const int half = tid >> 5;        // 0: wn=0 (warps 0,1)  1: wn=32 (warps 2,3)
        const int cc = tid & 31;
        float ssum = sred[(half * 2 + 0) * 32 + cc] + sred[(half * 2 + 1) * 32 + cc];
        g_partialB[(size_t)(bm >> 6) * R + bn + half * 32 + cc] = ssum;
    }
#undef ISSUE_STAGE
}

// ---------------- final deterministic reduce over chunks ----------------
__global__ void reduce_kernel(float* __restrict__ out) {
    int r = blockIdx.x * blockDim.x + threadIdx.x;
    float s = 0.f;
    #pragma unroll
    for (int c = 0; c < NCHUNKS; c++) s += g_partialA[c * R + r];
    #pragma unroll
    for (int m = 0; m < 16; m++) s += g_partialB[m * R + r];
    out[r] = s;
}

// ---------------- launch ----------------
extern "C" void kernel_launch(void* const* d_in, const int* in_sizes, int n_in,
                              void* d_out, int out_size) {
    const float* S    = (const float*)d_in[0];
    const float* E    = (const float*)d_in[1];
    const float* I    = (const float*)d_in[2];
    const float* T    = (const float*)d_in[3];
    const float* N    = (const float*)d_in[4];
    const float* S_E  = (const float*)d_in[5];
    const float* E_I  = (const float*)d_in[6];
    const float* I_T  = (const float*)d_in[7];
    const float* I_U  = (const float*)d_in[8];
    const float* T_R  = (const float*)d_in[9];
    const float* T_D  = (const float*)d_in[10];
    const float* adj  = (const float*)d_in[11];
    const float* ldE  = (const float*)d_in[12];
    const float* ldI  = (const float*)d_in[13];
    const float* ldT  = (const float*)d_in[14];
    const float* detr = (const float*)d_in[15];
    const float* recr = (const float*)d_in[16];
    const float* cont = (const float*)d_in[17];
    float* out = (float*)d_out;

    uint8_t* I8;      cudaGetSymbolAddress((void**)&I8, g_I8);
    uint8_t* ADJ8;    cudaGetSymbolAddress((void**)&ADJ8, g_ADJ8);

    cudaFuncSetAttribute(gemm_eit, cudaFuncAttributeMaxDynamicSharedMemorySize, GEMM_SMEM);

    // 1) cvt phase (DRAM-bound, feeds the GEMM)
    cvt_adj_an<<<R, 128>>>(adj, N, ADJ8);
    cvt_I8<<<512, 256>>>(I, I8, (int)((size_t)D * R / 8));

    // 2) merged GEMM(+fused S epilogue) + EIT: 2048 mixed CTAs
    gemm_eit<<<2048, 128, GEMM_SMEM>>>(
        I8, ADJ8, S, S_E, cont,
        E, I, T, E_I, I_T, I_U, T_R, T_D, detr, recr, ldE, ldI, ldT);

    // 3) final reduce
    reduce_kernel<<<R / 128, 128>>>(out);
}